// round 15
// baseline (speedup 1.0000x reference)
#include <cuda_runtime.h>
#include <cstdint>
#include <mma.h>
#include <math.h>

using namespace nvcuda;

// Problem constants (fixed by the dataset)
#define N_ROWS 8192
#define M_ROWS 8192
#define FDIM   512
#define HDIM   512
#define NVIEW  3

// ---------------------------------------------------------------------------
// Scratch (device globals — no allocation allowed anywhere)
// ---------------------------------------------------------------------------
__device__ float g_cz[(size_t)N_ROWS * FDIM];             // tf32(cz)
__device__ float g_z [(size_t)NVIEW * M_ROWS * FDIM];     // tf32(zs)
__device__ float g_wq[(size_t)HDIM * FDIM];               // tf32(Wq)
__device__ float g_wk[(size_t)HDIM * FDIM];               // tf32(Wk)
__device__ float g_q[(size_t)N_ROWS * HDIM];              // elu(cz@WqT), tf32-rounded
__device__ float g_k[(size_t)NVIEW * M_ROWS * HDIM];      // elu(zs_v@WkT), tf32-rounded
__device__ float g_GCp[(size_t)4 * HDIM * 3072];          // split-K partials of [G|C]
__device__ float g_GC[(size_t)HDIM * 3072];               // [h][v*1024 + (G | C)], tf32
__device__ float g_TU[(size_t)N_ROWS * 3072];             // q @ g_GC

__device__ __forceinline__ float to_tf32(float x) {
    unsigned u;
    asm("cvt.rna.tf32.f32 %0, %1;" : "=r"(u) : "f"(x));
    return __uint_as_float(u);
}

// cp.async helpers (16B, L2-cached)
__device__ __forceinline__ void cpa16(uint32_t saddr, const float* gaddr) {
    asm volatile("cp.async.cg.shared.global [%0], [%1], 16;" :: "r"(saddr), "l"(gaddr));
}
__device__ __forceinline__ void cpa_commit() { asm volatile("cp.async.commit_group;"); }
__device__ __forceinline__ void cpa_wait1()  { asm volatile("cp.async.wait_group 1;"); }

// ---------------------------------------------------------------------------
// Kernel 0: tf32-round a buffer (float4 granularity; sizes are multiples of 4)
// ---------------------------------------------------------------------------
__global__ void round_kernel(const float* __restrict__ in, float* __restrict__ out, int n4)
{
    int i = blockIdx.x * blockDim.x + threadIdx.x;
    if (i < n4) {
        float4 v = reinterpret_cast<const float4*>(in)[i];
        v.x = to_tf32(v.x); v.y = to_tf32(v.y); v.z = to_tf32(v.z); v.w = to_tf32(v.w);
        reinterpret_cast<float4*>(out)[i] = v;
    }
}

// ===========================================================================
// Kernel 1: projections  P = elu(X @ W^T), tf32-rounded output.
// CTA tile 128(m) x 256(h); 16 warps (4x4), warp tile 32x64 (2x4 frags).
// A = X rows; B(k=f,n=h) = W[h][f]: W rows staged natively, read col_major.
// K-chunk 32, cp.async 3-stage. grid = (hTile=2, mTile=64, src=4)
// ===========================================================================
__global__ __launch_bounds__(512, 1)
void proj_kernel()
{
    const int y = blockIdx.z;
    const float* X = (y == 0) ? g_cz : (g_z + (size_t)(y - 1) * M_ROWS * FDIM);
    const float* W = (y == 0) ? g_wq : g_wk;
    float*       O = (y == 0) ? g_q  : (g_k + (size_t)(y - 1) * M_ROWS * HDIM);
    const int rowBase = blockIdx.y * 128;
    const int hBase   = blockIdx.x * 256;

    extern __shared__ float sm[];                  // 3 x (A[128][36] + W[256][36])
    const uint32_t smb = (uint32_t)__cvta_generic_to_shared(sm);
    const int STG = 13824;                          // floats per stage

    const int tid = threadIdx.x;
    const int wid = tid >> 5;
    const int wm = wid & 3, wn = wid >> 2;
    const int r0 = tid >> 3, c0 = (tid & 7) * 4;   // A: 64 rows/half; W: 64 rows/quarter

    wmma::fragment<wmma::accumulator, 16, 16, 8, float> acc[2][4];
#pragma unroll
    for (int i = 0; i < 2; ++i)
#pragma unroll
        for (int j = 0; j < 4; ++j) wmma::fill_fragment(acc[i][j], 0.0f);

    auto issue = [&](int ch) {
        const int kB = ch * 32;
        uint32_t ap = smb + (uint32_t)((ch % 3) * STG) * 4;
        uint32_t wp = ap + 4608 * 4;
        cpa16(ap + (uint32_t)(r0 * 36 + c0) * 4,        &X[(size_t)(rowBase + r0) * 512 + kB + c0]);
        cpa16(ap + (uint32_t)((r0 + 64) * 36 + c0) * 4, &X[(size_t)(rowBase + r0 + 64) * 512 + kB + c0]);
#pragma unroll
        for (int qq = 0; qq < 4; ++qq)
            cpa16(wp + (uint32_t)((r0 + qq * 64) * 36 + c0) * 4,
                  &W[(size_t)(hBase + r0 + qq * 64) * 512 + kB + c0]);
    };

    issue(0); cpa_commit();
    issue(1); cpa_commit();

    for (int ch = 0; ch < 16; ++ch) {
        cpa_wait1();
        __syncthreads();
        const float* ap = sm + (ch % 3) * STG;
        const float* wp = ap + 4608;
#pragma unroll
        for (int t = 0; t < 4; ++t) {
            wmma::fragment<wmma::matrix_a, 16, 16, 8, wmma::precision::tf32, wmma::row_major> a0, a1;
            wmma::load_matrix_sync(a0, ap + (wm * 32 + 0)  * 36 + t * 8, 36);
            wmma::load_matrix_sync(a1, ap + (wm * 32 + 16) * 36 + t * 8, 36);
#pragma unroll
            for (int j = 0; j < 4; ++j) {
                wmma::fragment<wmma::matrix_b, 16, 16, 8, wmma::precision::tf32, wmma::col_major> b;
                wmma::load_matrix_sync(b, wp + (wn * 64 + j * 16) * 36 + t * 8, 36);
                wmma::mma_sync(acc[0][j], a0, b, acc[0][j]);
                wmma::mma_sync(acc[1][j], a1, b, acc[1][j]);
            }
        }
        if (ch + 2 < 16) issue(ch + 2);
        cpa_commit();
    }

    // Epilogue: elu + tf32 elementwise on fragments, store direct to global.
#pragma unroll
    for (int i = 0; i < 2; ++i)
#pragma unroll
        for (int j = 0; j < 4; ++j) {
#pragma unroll
            for (int e = 0; e < acc[i][j].num_elements; ++e) {
                float x = acc[i][j].x[e];
                x = (x > 0.0f) ? x : expm1f(x);
                acc[i][j].x[e] = to_tf32(x);
            }
            wmma::store_matrix_sync(
                O + (size_t)(rowBase + wm * 32 + i * 16) * 512 + hBase + wn * 64 + j * 16,
                acc[i][j], 512, wmma::mem_row_major);
        }
}

// ===========================================================================
// Kernel 2: gram — per view v:  G_v = k_v^T k_v,  C_v = k_v^T zv.
// CTA 128(h) x 256(j); warp tile 32x64. A = k^T staged natively k_s[m][h],
// read matrix_a col_major. split-K=4 (2048 m each), K-chunk 32, 3-stage.
// grid = (jTile=4, hTile=4, v*4+ks = 12)
// ===========================================================================
__global__ __launch_bounds__(512, 1)
void gram_kernel()
{
    const int jTile = blockIdx.x;
    const int hTile = blockIdx.y;
    const int v  = blockIdx.z >> 2;
    const int ks = blockIdx.z & 3;
    const int hBase  = hTile * 128;
    const int jBase  = jTile * 256;                 // 0,256 -> G; 512,768 -> C
    const int mBase0 = ks * 2048;

    const float* asrc = g_k + (size_t)v * M_ROWS * HDIM;
    const bool  isG  = (jBase < 512);
    const float* bsrc = isG ? (g_k + (size_t)v * M_ROWS * HDIM)
                            : (g_z + (size_t)v * M_ROWS * FDIM);
    const int cBase = isG ? jBase : (jBase - 512);

    extern __shared__ float sm[];                  // 3 x (k_s[32][132] + b_s[32][260])
    const uint32_t smb = (uint32_t)__cvta_generic_to_shared(sm);
    const int STG = 12544;

    const int tid = threadIdx.x;
    const int wid = tid >> 5;
    const int wm = wid & 3, wn = wid >> 2;
    const int m0 = tid >> 5, c0 = (tid & 31) * 4;  // 16 m-rows per half

    wmma::fragment<wmma::accumulator, 16, 16, 8, float> acc[2][4];
#pragma unroll
    for (int i = 0; i < 2; ++i)
#pragma unroll
        for (int j = 0; j < 4; ++j) wmma::fill_fragment(acc[i][j], 0.0f);

    auto issue = [&](int ch) {
        const int mB = mBase0 + ch * 32;
        uint32_t kp = smb + (uint32_t)((ch % 3) * STG) * 4;
        uint32_t bp = kp + 4224 * 4;
        cpa16(kp + (uint32_t)(m0 * 132 + c0) * 4,        &asrc[(size_t)(mB + m0) * 512 + hBase + c0]);
        cpa16(kp + (uint32_t)((m0 + 16) * 132 + c0) * 4, &asrc[(size_t)(mB + m0 + 16) * 512 + hBase + c0]);
#pragma unroll
        for (int hh = 0; hh < 2; ++hh) {
            cpa16(bp + (uint32_t)(m0 * 260 + c0 + hh * 128) * 4,
                  &bsrc[(size_t)(mB + m0) * 512 + cBase + c0 + hh * 128]);
            cpa16(bp + (uint32_t)((m0 + 16) * 260 + c0 + hh * 128) * 4,
                  &bsrc[(size_t)(mB + m0 + 16) * 512 + cBase + c0 + hh * 128]);
        }
    };

    issue(0); cpa_commit();
    issue(1); cpa_commit();

    for (int ch = 0; ch < 64; ++ch) {
        cpa_wait1();
        __syncthreads();
        const float* kp = sm + (ch % 3) * STG;
        const float* bp = kp + 4224;
#pragma unroll
        for (int t = 0; t < 4; ++t) {
            // A col_major: A(h,m) at k_s[m*132 + h]
            wmma::fragment<wmma::matrix_a, 16, 16, 8, wmma::precision::tf32, wmma::col_major> a0, a1;
            wmma::load_matrix_sync(a0, kp + (t * 8) * 132 + wm * 32 + 0,  132);
            wmma::load_matrix_sync(a1, kp + (t * 8) * 132 + wm * 32 + 16, 132);
#pragma unroll
            for (int j = 0; j < 4; ++j) {
                wmma::fragment<wmma::matrix_b, 16, 16, 8, wmma::precision::tf32, wmma::row_major> b;
                wmma::load_matrix_sync(b, bp + (t * 8) * 260 + wn * 64 + j * 16, 260);
                wmma::mma_sync(acc[0][j], a0, b, acc[0][j]);
                wmma::mma_sync(acc[1][j], a1, b, acc[1][j]);
            }
        }
        if (ch + 2 < 64) issue(ch + 2);
        cpa_commit();
    }

    float* op = g_GCp + ((size_t)ks * 512 + hBase + wm * 32) * 3072
                      + (size_t)(v * 1024 + jBase + wn * 64);
#pragma unroll
    for (int i = 0; i < 2; ++i)
#pragma unroll
        for (int j = 0; j < 4; ++j)
            wmma::store_matrix_sync(op + (size_t)(i * 16) * 3072 + j * 16,
                                    acc[i][j], 3072, wmma::mem_row_major);
}

// ---------------------------------------------------------------------------
// Kernel 3: reduce split-K partials, tf32-round -> g_GC
// ---------------------------------------------------------------------------
__global__ void gramreduce_kernel()
{
    const size_t i = ((size_t)blockIdx.x * 512 + threadIdx.x) * 4;
    const size_t S = (size_t)512 * 3072;
    float4 a = *reinterpret_cast<const float4*>(&g_GCp[i]);
    float4 b = *reinterpret_cast<const float4*>(&g_GCp[i + S]);
    float4 c = *reinterpret_cast<const float4*>(&g_GCp[i + 2 * S]);
    float4 d = *reinterpret_cast<const float4*>(&g_GCp[i + 3 * S]);
    float4 o;
    o.x = to_tf32(a.x + b.x + c.x + d.x);
    o.y = to_tf32(a.y + b.y + c.y + d.y);
    o.z = to_tf32(a.z + b.z + c.z + d.z);
    o.w = to_tf32(a.w + b.w + c.w + d.w);
    *reinterpret_cast<float4*>(&g_GC[i]) = o;
}

// ===========================================================================
// Kernel 4: big GEMM  g_TU = g_q [8192x512] @ g_GC [512x3072]
// CTA 128(i) x 256(n); warp tile 32x64. cp.async 3-stage. grid = (12, 64)
// ===========================================================================
__global__ __launch_bounds__(512, 1)
void biggemm_kernel()
{
    const int nBase = blockIdx.x * 256;
    const int iBase = blockIdx.y * 128;

    extern __shared__ float sm[];                  // 3 x (a_s[128][36] + b_s[32][260])
    const uint32_t smb = (uint32_t)__cvta_generic_to_shared(sm);
    const int STG = 12928;

    const int tid = threadIdx.x;
    const int wid = tid >> 5;
    const int wm = wid & 3, wn = wid >> 2;
    const int ra = tid >> 3, ca = (tid & 7) * 4;    // A: 64 rows/half
    const int mb = tid >> 5, cb = (tid & 31) * 4;   // B: 16 rows/half, 2 col-halves

    wmma::fragment<wmma::accumulator, 16, 16, 8, float> acc[2][4];
#pragma unroll
    for (int i = 0; i < 2; ++i)
#pragma unroll
        for (int j = 0; j < 4; ++j) wmma::fill_fragment(acc[i][j], 0.0f);

    auto issue = [&](int ch) {
        const int kB = ch * 32;
        uint32_t ap = smb + (uint32_t)((ch % 3) * STG) * 4;
        uint32_t bp = ap + 4608 * 4;
        cpa16(ap + (uint32_t)(ra * 36 + ca) * 4,         &g_q[(size_t)(iBase + ra) * 512 + kB + ca]);
        cpa16(ap + (uint32_t)((ra + 64) * 36 + ca) * 4,  &g_q[(size_t)(iBase + ra + 64) * 512 + kB + ca]);
#pragma unroll
        for (int hh = 0; hh < 2; ++hh) {
            cpa16(bp + (uint32_t)(mb * 260 + cb + hh * 128) * 4,
                  &g_GC[(size_t)(kB + mb) * 3072 + nBase + cb + hh * 128]);
            cpa16(bp + (uint32_t)((mb + 16) * 260 + cb + hh * 128) * 4,
                  &g_GC[(size_t)(kB + mb + 16) * 3072 + nBase + cb + hh * 128]);
        }
    };

    issue(0); cpa_commit();
    issue(1); cpa_commit();

    for (int ch = 0; ch < 16; ++ch) {
        cpa_wait1();
        __syncthreads();
        const float* ap = sm + (ch % 3) * STG;
        const float* bp = ap + 4608;
#pragma unroll
        for (int t = 0; t < 4; ++t) {
            wmma::fragment<wmma::matrix_a, 16, 16, 8, wmma::precision::tf32, wmma::row_major> a0, a1;
            wmma::load_matrix_sync(a0, ap + (wm * 32 + 0)  * 36 + t * 8, 36);
            wmma::load_matrix_sync(a1, ap + (wm * 32 + 16) * 36 + t * 8, 36);
#pragma unroll
            for (int j = 0; j < 4; ++j) {
                wmma::fragment<wmma::matrix_b, 16, 16, 8, wmma::precision::tf32, wmma::row_major> b;
                wmma::load_matrix_sync(b, bp + (t * 8) * 260 + wn * 64 + j * 16, 260);
                wmma::mma_sync(acc[0][j], a0, b, acc[0][j]);
                wmma::mma_sync(acc[1][j], a1, b, acc[1][j]);
            }
        }
        if (ch + 2 < 16) issue(ch + 2);
        cpa_commit();
    }

    float* op = g_TU + (size_t)(iBase + wm * 32) * 3072 + (size_t)(nBase + wn * 64);
#pragma unroll
    for (int i = 0; i < 2; ++i)
#pragma unroll
        for (int j = 0; j < 4; ++j)
            wmma::store_matrix_sync(op + (size_t)(i * 16) * 3072 + j * 16,
                                    acc[i][j], 3072, wmma::mem_row_major);
}

// ---------------------------------------------------------------------------
// Kernel 5: combine — per row i:
//   sumsq_v = sum_h T_v[i][h] * q[i][h]   (= q_i G_v q_i^T)
//   out[i][f] = cz[i][f] + sum_v U_v[i][f] / max(sqrt(sumsq_v), eps)
// ---------------------------------------------------------------------------
__global__ void combine_kernel(const float* __restrict__ cz, float* __restrict__ out)
{
    const int row = blockIdx.x;
    const int tid = threadIdx.x;   // 128
    __shared__ float red[3][128];
    __shared__ float inv_s[3];

    const float* Trow = g_TU + (size_t)row * 3072;
    const float* qrow = g_q  + (size_t)row * 512;

    float p0 = 0.0f, p1 = 0.0f, p2 = 0.0f;
#pragma unroll
    for (int t = 0; t < 4; ++t) {
        int h = tid + t * 128;
        float qh = qrow[h];
        p0 += Trow[h]        * qh;
        p1 += Trow[1024 + h] * qh;
        p2 += Trow[2048 + h] * qh;
    }
    red[0][tid] = p0; red[1][tid] = p1; red[2][tid] = p2;
    __syncthreads();
#pragma unroll
    for (int s = 64; s > 0; s >>= 1) {
        if (tid < s) {
            red[0][tid] += red[0][tid + s];
            red[1][tid] += red[1][tid + s];
            red[2][tid] += red[2][tid + s];
        }
        __syncthreads();
    }
    if (tid < 3) {
        float ss = fmaxf(red[tid][0], 0.0f);
        inv_s[tid] = 1.0f / fmaxf(sqrtf(ss), 1e-12f);
    }
    __syncthreads();

    const int f = tid * 4;
    float4 o = *reinterpret_cast<const float4*>(&cz[(size_t)row * 512 + f]);
#pragma unroll
    for (int v = 0; v < 3; ++v) {
        float iv = inv_s[v];
        float4 u = *reinterpret_cast<const float4*>(&Trow[v * 1024 + 512 + f]);
        o.x += u.x * iv; o.y += u.y * iv; o.z += u.z * iv; o.w += u.w * iv;
    }
    *reinterpret_cast<float4*>(&out[(size_t)row * 512 + f]) = o;
}

// ---------------------------------------------------------------------------
extern "C" void kernel_launch(void* const* d_in, const int* in_sizes, int n_in,
                              void* d_out, int out_size)
{
    const float* cz = (const float*)d_in[0];
    const float* zs = (const float*)d_in[1];
    const float* Wq = (const float*)d_in[2];
    const float* Wk = (const float*)d_in[3];
    float* out = (float*)d_out;

    const int smem_proj = 3 * 13824 * (int)sizeof(float);   // 165,888 B
    const int smem_gram = 3 * 12544 * (int)sizeof(float);   // 150,528 B
    const int smem_bg   = 3 * 12928 * (int)sizeof(float);   // 155,136 B

    cudaFuncSetAttribute(proj_kernel,    cudaFuncAttributeMaxDynamicSharedMemorySize, smem_proj);
    cudaFuncSetAttribute(gram_kernel,    cudaFuncAttributeMaxDynamicSharedMemorySize, smem_gram);
    cudaFuncSetAttribute(biggemm_kernel, cudaFuncAttributeMaxDynamicSharedMemorySize, smem_bg);

    // Resolve device-global addresses (host-side; graph-capture safe).
    float *p_cz, *p_z, *p_wq, *p_wk;
    cudaGetSymbolAddress((void**)&p_cz, g_cz);
    cudaGetSymbolAddress((void**)&p_z,  g_z);
    cudaGetSymbolAddress((void**)&p_wq, g_wq);
    cudaGetSymbolAddress((void**)&p_wk, g_wk);

    // Pre-round all GEMM inputs to tf32 once (elementwise, float4).
    round_kernel<<<(N_ROWS * FDIM / 4 + 255) / 256, 256>>>(cz, p_cz, N_ROWS * FDIM / 4);
    round_kernel<<<(NVIEW * M_ROWS * FDIM / 4 + 255) / 256, 256>>>(zs, p_z, NVIEW * M_ROWS * FDIM / 4);
    round_kernel<<<(HDIM * FDIM / 4 + 255) / 256, 256>>>(Wq, p_wq, HDIM * FDIM / 4);
    round_kernel<<<(HDIM * FDIM / 4 + 255) / 256, 256>>>(Wk, p_wk, HDIM * FDIM / 4);

    proj_kernel<<<dim3(2, 64, 4), 512, smem_proj>>>();
    gram_kernel<<<dim3(4, 4, 12), 512, smem_gram>>>();
    gramreduce_kernel<<<768, 512>>>();
    biggemm_kernel<<<dim3(12, 64), 512, smem_bg>>>();
    combine_kernel<<<8192, 128>>>(cz, out);
}

// round 16
// speedup vs baseline: 1.1671x; 1.1671x over previous
#include <cuda_runtime.h>
#include <cstdint>
#include <mma.h>
#include <math.h>

using namespace nvcuda;

// Problem constants (fixed by the dataset)
#define N_ROWS 8192
#define M_ROWS 8192
#define FDIM   512
#define HDIM   512
#define NVIEW  3

// ---------------------------------------------------------------------------
// Scratch (device globals — no allocation allowed anywhere)
// ---------------------------------------------------------------------------
__device__ float g_cz[(size_t)N_ROWS * FDIM];             // tf32(cz)
__device__ float g_z [(size_t)NVIEW * M_ROWS * FDIM];     // tf32(zs)
__device__ float g_wq[(size_t)HDIM * FDIM];               // tf32(Wq)
__device__ float g_wk[(size_t)HDIM * FDIM];               // tf32(Wk)
__device__ float g_q[(size_t)N_ROWS * HDIM];              // elu(cz@WqT), tf32-rounded
__device__ float g_k[(size_t)NVIEW * M_ROWS * HDIM];      // elu(zs_v@WkT), tf32-rounded
__device__ float g_GCp[(size_t)4 * HDIM * 3072];          // split-K partials of [G|C]
__device__ float g_GC[(size_t)HDIM * 3072];               // [h][v*1024 + (G | C)], tf32
__device__ float g_TU[(size_t)N_ROWS * 3072];             // q @ g_GC

__device__ __forceinline__ float to_tf32(float x) {
    unsigned u;
    asm("cvt.rna.tf32.f32 %0, %1;" : "=r"(u) : "f"(x));
    return __uint_as_float(u);
}

// cp.async helpers (16B, L2-cached)
__device__ __forceinline__ void cpa16(uint32_t saddr, const float* gaddr) {
    asm volatile("cp.async.cg.shared.global [%0], [%1], 16;" :: "r"(saddr), "l"(gaddr));
}
__device__ __forceinline__ void cpa_commit() { asm volatile("cp.async.commit_group;"); }
__device__ __forceinline__ void cpa_wait1()  { asm volatile("cp.async.wait_group 1;"); }

// ---------------------------------------------------------------------------
// Kernel 0: tf32-round a buffer (float4 granularity; sizes are multiples of 4)
// ---------------------------------------------------------------------------
__global__ void round_kernel(const float* __restrict__ in, float* __restrict__ out, int n4)
{
    int i = blockIdx.x * blockDim.x + threadIdx.x;
    if (i < n4) {
        float4 v = reinterpret_cast<const float4*>(in)[i];
        v.x = to_tf32(v.x); v.y = to_tf32(v.y); v.z = to_tf32(v.z); v.w = to_tf32(v.w);
        reinterpret_cast<float4*>(out)[i] = v;
    }
}

// ===========================================================================
// Kernel 1: projections  P = elu(X @ W^T), tf32-rounded output.
// CTA tile 128(m) x 128(h); 256 threads = 8 warps (4m x 2n), warp tile 32x64.
// A = X rows; B(k=f,n=h) = W[h][f]: W rows staged natively, read col_major.
// K-chunk 32, cp.async 3-stage. Occupancy 2 CTAs/SM.
// grid = (hTile=4, mTile=64, src=4)
// ===========================================================================
__global__ __launch_bounds__(256, 2)
void proj_kernel()
{
    const int y = blockIdx.z;
    const float* X = (y == 0) ? g_cz : (g_z + (size_t)(y - 1) * M_ROWS * FDIM);
    const float* W = (y == 0) ? g_wq : g_wk;
    float*       O = (y == 0) ? g_q  : (g_k + (size_t)(y - 1) * M_ROWS * HDIM);
    const int rowBase = blockIdx.y * 128;
    const int hBase   = blockIdx.x * 128;

    extern __shared__ float sm[];                  // 3 x (A[128][36] + W[128][36])
    const uint32_t smb = (uint32_t)__cvta_generic_to_shared(sm);
    const int STG = 9216;                           // floats per stage

    const int tid = threadIdx.x;
    const int wid = tid >> 5;
    const int wm = wid & 3, wn = wid >> 2;          // wm 0..3, wn 0..1

    wmma::fragment<wmma::accumulator, 16, 16, 8, float> acc[2][4];
#pragma unroll
    for (int i = 0; i < 2; ++i)
#pragma unroll
        for (int j = 0; j < 4; ++j) wmma::fill_fragment(acc[i][j], 0.0f);

    auto issue = [&](int ch) {
        const int kB = ch * 32;
        uint32_t ap = smb + (uint32_t)((ch % 3) * STG) * 4;
        uint32_t wp = ap + 4608 * 4;
#pragma unroll
        for (int i = 0; i < 4; ++i) {
            int idx = tid + i * 256;
            int r = idx >> 3, c = (idx & 7) * 4;
            cpa16(ap + (uint32_t)(r * 36 + c) * 4, &X[(size_t)(rowBase + r) * 512 + kB + c]);
            cpa16(wp + (uint32_t)(r * 36 + c) * 4, &W[(size_t)(hBase + r) * 512 + kB + c]);
        }
    };

    issue(0); cpa_commit();
    issue(1); cpa_commit();

    for (int ch = 0; ch < 16; ++ch) {
        cpa_wait1();
        __syncthreads();
        const float* ap = sm + (ch % 3) * STG;
        const float* wp = ap + 4608;
#pragma unroll
        for (int t = 0; t < 4; ++t) {
            wmma::fragment<wmma::matrix_a, 16, 16, 8, wmma::precision::tf32, wmma::row_major> a0, a1;
            wmma::load_matrix_sync(a0, ap + (wm * 32 + 0)  * 36 + t * 8, 36);
            wmma::load_matrix_sync(a1, ap + (wm * 32 + 16) * 36 + t * 8, 36);
#pragma unroll
            for (int j = 0; j < 4; ++j) {
                wmma::fragment<wmma::matrix_b, 16, 16, 8, wmma::precision::tf32, wmma::col_major> b;
                wmma::load_matrix_sync(b, wp + (wn * 64 + j * 16) * 36 + t * 8, 36);
                wmma::mma_sync(acc[0][j], a0, b, acc[0][j]);
                wmma::mma_sync(acc[1][j], a1, b, acc[1][j]);
            }
        }
        if (ch + 2 < 16) issue(ch + 2);
        cpa_commit();
    }

    // Epilogue: elu + tf32 elementwise on fragments, store direct to global.
#pragma unroll
    for (int i = 0; i < 2; ++i)
#pragma unroll
        for (int j = 0; j < 4; ++j) {
#pragma unroll
            for (int e = 0; e < acc[i][j].num_elements; ++e) {
                float x = acc[i][j].x[e];
                x = (x > 0.0f) ? x : expm1f(x);
                acc[i][j].x[e] = to_tf32(x);
            }
            wmma::store_matrix_sync(
                O + (size_t)(rowBase + wm * 32 + i * 16) * 512 + hBase + wn * 64 + j * 16,
                acc[i][j], 512, wmma::mem_row_major);
        }
}

// ===========================================================================
// Kernel 2: gram — per view v:  G_v = k_v^T k_v,  C_v = k_v^T zv.
// CTA 128(h) x 128(j); 256 threads, 8 warps (4m x 2n), warp tile 32x64.
// A = k^T staged natively k_s[m][h], read matrix_a col_major.
// split-K=4 (2048 m each), K-chunk 32, 3-stage. Occupancy 2.
// grid = (jTile=8, hTile=4, v*4+ks = 12)
// ===========================================================================
__global__ __launch_bounds__(256, 2)
void gram_kernel()
{
    const int jTile = blockIdx.x;
    const int hTile = blockIdx.y;
    const int v  = blockIdx.z >> 2;
    const int ks = blockIdx.z & 3;
    const int hBase  = hTile * 128;
    const int jBase  = jTile * 128;
    const int mBase0 = ks * 2048;

    const float* asrc = g_k + (size_t)v * M_ROWS * HDIM;
    const bool  isG  = (jBase < 512);
    const float* bsrc = isG ? (g_k + (size_t)v * M_ROWS * HDIM)
                            : (g_z + (size_t)v * M_ROWS * FDIM);
    const int cBase = isG ? jBase : (jBase - 512);

    extern __shared__ float sm[];                  // 3 x (k_s[32][132] + b_s[32][132])
    const uint32_t smb = (uint32_t)__cvta_generic_to_shared(sm);
    const int STG = 8448;

    const int tid = threadIdx.x;
    const int wid = tid >> 5;
    const int wm = wid & 3, wn = wid >> 2;

    wmma::fragment<wmma::accumulator, 16, 16, 8, float> acc[2][4];
#pragma unroll
    for (int i = 0; i < 2; ++i)
#pragma unroll
        for (int j = 0; j < 4; ++j) wmma::fill_fragment(acc[i][j], 0.0f);

    auto issue = [&](int ch) {
        const int mB = mBase0 + ch * 32;
        uint32_t kp = smb + (uint32_t)((ch % 3) * STG) * 4;
        uint32_t bp = kp + 4224 * 4;
#pragma unroll
        for (int i = 0; i < 4; ++i) {
            int idx = tid + i * 256;
            int m = idx >> 5, c = (idx & 31) * 4;
            cpa16(kp + (uint32_t)(m * 132 + c) * 4, &asrc[(size_t)(mB + m) * 512 + hBase + c]);
            cpa16(bp + (uint32_t)(m * 132 + c) * 4, &bsrc[(size_t)(mB + m) * 512 + cBase + c]);
        }
    };

    issue(0); cpa_commit();
    issue(1); cpa_commit();

    for (int ch = 0; ch < 64; ++ch) {
        cpa_wait1();
        __syncthreads();
        const float* kp = sm + (ch % 3) * STG;
        const float* bp = kp + 4224;
#pragma unroll
        for (int t = 0; t < 4; ++t) {
            // A col_major: A(h,m) at k_s[m*132 + h]
            wmma::fragment<wmma::matrix_a, 16, 16, 8, wmma::precision::tf32, wmma::col_major> a0, a1;
            wmma::load_matrix_sync(a0, kp + (t * 8) * 132 + wm * 32 + 0,  132);
            wmma::load_matrix_sync(a1, kp + (t * 8) * 132 + wm * 32 + 16, 132);
#pragma unroll
            for (int j = 0; j < 4; ++j) {
                wmma::fragment<wmma::matrix_b, 16, 16, 8, wmma::precision::tf32, wmma::row_major> b;
                wmma::load_matrix_sync(b, bp + (t * 8) * 132 + wn * 64 + j * 16, 132);
                wmma::mma_sync(acc[0][j], a0, b, acc[0][j]);
                wmma::mma_sync(acc[1][j], a1, b, acc[1][j]);
            }
        }
        if (ch + 2 < 64) issue(ch + 2);
        cpa_commit();
    }

    float* op = g_GCp + ((size_t)ks * 512 + hBase + wm * 32) * 3072
                      + (size_t)(v * 1024 + jBase + wn * 64);
#pragma unroll
    for (int i = 0; i < 2; ++i)
#pragma unroll
        for (int j = 0; j < 4; ++j)
            wmma::store_matrix_sync(op + (size_t)(i * 16) * 3072 + j * 16,
                                    acc[i][j], 3072, wmma::mem_row_major);
}

// ---------------------------------------------------------------------------
// Kernel 3: reduce split-K partials, tf32-round -> g_GC
// ---------------------------------------------------------------------------
__global__ void gramreduce_kernel()
{
    const size_t i = ((size_t)blockIdx.x * 512 + threadIdx.x) * 4;
    const size_t S = (size_t)512 * 3072;
    float4 a = *reinterpret_cast<const float4*>(&g_GCp[i]);
    float4 b = *reinterpret_cast<const float4*>(&g_GCp[i + S]);
    float4 c = *reinterpret_cast<const float4*>(&g_GCp[i + 2 * S]);
    float4 d = *reinterpret_cast<const float4*>(&g_GCp[i + 3 * S]);
    float4 o;
    o.x = to_tf32(a.x + b.x + c.x + d.x);
    o.y = to_tf32(a.y + b.y + c.y + d.y);
    o.z = to_tf32(a.z + b.z + c.z + d.z);
    o.w = to_tf32(a.w + b.w + c.w + d.w);
    *reinterpret_cast<float4*>(&g_GC[i]) = o;
}

// ===========================================================================
// Kernel 4: big GEMM  g_TU = g_q [8192x512] @ g_GC [512x3072]
// CTA 128(i) x 128(n); 256 threads, 8 warps (4m x 2n), warp tile 32x64.
// cp.async 3-stage. Occupancy 2. grid = (24, 64)
// ===========================================================================
__global__ __launch_bounds__(256, 2)
void biggemm_kernel()
{
    const int nBase = blockIdx.x * 128;
    const int iBase = blockIdx.y * 128;

    extern __shared__ float sm[];                  // 3 x (a_s[128][36] + b_s[32][132])
    const uint32_t smb = (uint32_t)__cvta_generic_to_shared(sm);
    const int STG = 8832;

    const int tid = threadIdx.x;
    const int wid = tid >> 5;
    const int wm = wid & 3, wn = wid >> 2;

    wmma::fragment<wmma::accumulator, 16, 16, 8, float> acc[2][4];
#pragma unroll
    for (int i = 0; i < 2; ++i)
#pragma unroll
        for (int j = 0; j < 4; ++j) wmma::fill_fragment(acc[i][j], 0.0f);

    auto issue = [&](int ch) {
        const int kB = ch * 32;
        uint32_t ap = smb + (uint32_t)((ch % 3) * STG) * 4;
        uint32_t bp = ap + 4608 * 4;
#pragma unroll
        for (int i = 0; i < 4; ++i) {
            int idx = tid + i * 256;
            {   // A: 128 rows x 8 float4
                int r = idx >> 3, c = (idx & 7) * 4;
                cpa16(ap + (uint32_t)(r * 36 + c) * 4, &g_q[(size_t)(iBase + r) * 512 + kB + c]);
            }
            {   // B: 32 rows x 32 float4
                int m = idx >> 5, c = (idx & 31) * 4;
                cpa16(bp + (uint32_t)(m * 132 + c) * 4, &g_GC[(size_t)(kB + m) * 3072 + nBase + c]);
            }
        }
    };

    issue(0); cpa_commit();
    issue(1); cpa_commit();

    for (int ch = 0; ch < 16; ++ch) {
        cpa_wait1();
        __syncthreads();
        const float* ap = sm + (ch % 3) * STG;
        const float* bp = ap + 4608;
#pragma unroll
        for (int t = 0; t < 4; ++t) {
            wmma::fragment<wmma::matrix_a, 16, 16, 8, wmma::precision::tf32, wmma::row_major> a0, a1;
            wmma::load_matrix_sync(a0, ap + (wm * 32 + 0)  * 36 + t * 8, 36);
            wmma::load_matrix_sync(a1, ap + (wm * 32 + 16) * 36 + t * 8, 36);
#pragma unroll
            for (int j = 0; j < 4; ++j) {
                wmma::fragment<wmma::matrix_b, 16, 16, 8, wmma::precision::tf32, wmma::row_major> b;
                wmma::load_matrix_sync(b, bp + (t * 8) * 132 + wn * 64 + j * 16, 132);
                wmma::mma_sync(acc[0][j], a0, b, acc[0][j]);
                wmma::mma_sync(acc[1][j], a1, b, acc[1][j]);
            }
        }
        if (ch + 2 < 16) issue(ch + 2);
        cpa_commit();
    }

    float* op = g_TU + (size_t)(iBase + wm * 32) * 3072 + (size_t)(nBase + wn * 64);
#pragma unroll
    for (int i = 0; i < 2; ++i)
#pragma unroll
        for (int j = 0; j < 4; ++j)
            wmma::store_matrix_sync(op + (size_t)(i * 16) * 3072 + j * 16,
                                    acc[i][j], 3072, wmma::mem_row_major);
}

// ---------------------------------------------------------------------------
// Kernel 5: combine — per row i:
//   sumsq_v = sum_h T_v[i][h] * q[i][h]   (= q_i G_v q_i^T)
//   out[i][f] = cz[i][f] + sum_v U_v[i][f] / max(sqrt(sumsq_v), eps)
// ---------------------------------------------------------------------------
__global__ void combine_kernel(const float* __restrict__ cz, float* __restrict__ out)
{
    const int row = blockIdx.x;
    const int tid = threadIdx.x;   // 128
    __shared__ float red[3][128];
    __shared__ float inv_s[3];

    const float* Trow = g_TU + (size_t)row * 3072;
    const float* qrow = g_q  + (size_t)row * 512;

    float p0 = 0.0f, p1 = 0.0f, p2 = 0.0f;
#pragma unroll
    for (int t = 0; t < 4; ++t) {
        int h = tid + t * 128;
        float qh = qrow[h];
        p0 += Trow[h]        * qh;
        p1 += Trow[1024 + h] * qh;
        p2 += Trow[2048 + h] * qh;
    }
    red[0][tid] = p0; red[1][tid] = p1; red[2][tid] = p2;
    __syncthreads();
#pragma unroll
    for (int s = 64; s > 0; s >>= 1) {
        if (tid < s) {
            red[0][tid] += red[0][tid + s];
            red[1][tid] += red[1][tid + s];
            red[2][tid] += red[2][tid + s];
        }
        __syncthreads();
    }
    if (tid < 3) {
        float ss = fmaxf(red[tid][0], 0.0f);
        inv_s[tid] = 1.0f / fmaxf(sqrtf(ss), 1e-12f);
    }
    __syncthreads();

    const int f = tid * 4;
    float4 o = *reinterpret_cast<const float4*>(&cz[(size_t)row * 512 + f]);
#pragma unroll
    for (int v = 0; v < 3; ++v) {
        float iv = inv_s[v];
        float4 u = *reinterpret_cast<const float4*>(&Trow[v * 1024 + 512 + f]);
        o.x += u.x * iv; o.y += u.y * iv; o.z += u.z * iv; o.w += u.w * iv;
    }
    *reinterpret_cast<float4*>(&out[(size_t)row * 512 + f]) = o;
}

// ---------------------------------------------------------------------------
extern "C" void kernel_launch(void* const* d_in, const int* in_sizes, int n_in,
                              void* d_out, int out_size)
{
    const float* cz = (const float*)d_in[0];
    const float* zs = (const float*)d_in[1];
    const float* Wq = (const float*)d_in[2];
    const float* Wk = (const float*)d_in[3];
    float* out = (float*)d_out;

    const int smem_proj = 3 * 9216 * (int)sizeof(float);   // 110,592 B (x2 CTAs/SM)
    const int smem_gram = 3 * 8448 * (int)sizeof(float);   // 101,376 B (x2 CTAs/SM)
    const int smem_bg   = 3 * 8832 * (int)sizeof(float);   // 105,984 B (x2 CTAs/SM)

    cudaFuncSetAttribute(proj_kernel,    cudaFuncAttributeMaxDynamicSharedMemorySize, smem_proj);
    cudaFuncSetAttribute(gram_kernel,    cudaFuncAttributeMaxDynamicSharedMemorySize, smem_gram);
    cudaFuncSetAttribute(biggemm_kernel, cudaFuncAttributeMaxDynamicSharedMemorySize, smem_bg);

    // Resolve device-global addresses (host-side; graph-capture safe).
    float *p_cz, *p_z, *p_wq, *p_wk;
    cudaGetSymbolAddress((void**)&p_cz, g_cz);
    cudaGetSymbolAddress((void**)&p_z,  g_z);
    cudaGetSymbolAddress((void**)&p_wq, g_wq);
    cudaGetSymbolAddress((void**)&p_wk, g_wk);

    // Pre-round all GEMM inputs to tf32 once (elementwise, float4).
    round_kernel<<<(N_ROWS * FDIM / 4 + 255) / 256, 256>>>(cz, p_cz, N_ROWS * FDIM / 4);
    round_kernel<<<(NVIEW * M_ROWS * FDIM / 4 + 255) / 256, 256>>>(zs, p_z, NVIEW * M_ROWS * FDIM / 4);
    round_kernel<<<(HDIM * FDIM / 4 + 255) / 256, 256>>>(Wq, p_wq, HDIM * FDIM / 4);
    round_kernel<<<(HDIM * FDIM / 4 + 255) / 256, 256>>>(Wk, p_wk, HDIM * FDIM / 4);

    proj_kernel<<<dim3(4, 64, 4), 256, smem_proj>>>();
    gram_kernel<<<dim3(8, 4, 12), 256, smem_gram>>>();
    gramreduce_kernel<<<768, 512>>>();
    biggemm_kernel<<<dim3(24, 64), 256, smem_bg>>>();
    combine_kernel<<<8192, 128>>>(cz, out);
}